// round 9
// baseline (speedup 1.0000x reference)
#include <cuda_runtime.h>
#include <cuda_bf16.h>
#include <cuda_fp8.h>
#include <math.h>
#include <stdint.h>

#define Bb 2
#define Cc 512
#define Tt 16
#define NN 1024
#define HEADS 8
#define Dd 64
#define BT 32
#define C3 1536
#define C2 (Cc / 2)       // 256 k2-rows per GEMM reduction

typedef __nv_bfloat16 bf16;
typedef long long ll;

// ---------------- scratch (device globals) ----------------
__device__ __align__(16) uint16_t g_w8_sqkv[C2 * C3];   // fp8-pair units [k2][o]
__device__ __align__(16) uint16_t g_w8_sout[C2 * Cc];
__device__ __align__(16) uint16_t g_w8_tqkv[C2 * C3];
__device__ __align__(16) uint16_t g_w8_tout[C2 * Cc];
__device__ __align__(16) uint16_t g_x8[Bb * C2 * Tt * NN];      // x pairs [b][c2][tn]
__device__ __align__(16) bf16     g_sqkv[BT * C3 * NN];
__device__ __align__(16) bf16     g_ctx_ed[BT * HEADS * Dd * Dd];
__device__ __align__(16) uint16_t g_sattn8[BT * C2 * NN];       // sattn pairs [bt][c2][n], x16
__device__ __align__(16) uint16_t g_h18[Bb * C2 * Tt * NN];     // h1 pairs, x64
__device__ __align__(16) bf16     g_tqkv[Bb * C3 * Tt * NN];
__device__ __align__(16) uint16_t g_tout8[Bb * C2 * Tt * NN];   // tout pairs, x128

// ---------------- helpers ----------------
__device__ __forceinline__ uint32_t smem_u32(const void* p) {
    uint32_t a;
    asm("{ .reg .u64 t; cvta.to.shared.u64 t, %1; cvt.u32.u64 %0, t; }" : "=r"(a) : "l"(p));
    return a;
}
#define CP_ASYNC(dst, src) asm volatile("cp.async.cg.shared.global [%0],[%1],16;\n" :: "r"(dst), "l"(src) : "memory")
#define CP_COMMIT()        asm volatile("cp.async.commit_group;\n" ::: "memory")
#define CP_WAIT0()         asm volatile("cp.async.wait_group 0;\n" ::: "memory")
#define CP_WAIT1()         asm volatile("cp.async.wait_group 1;\n" ::: "memory")

#define LDSM_X4(r0,r1,r2,r3,addr) \
    asm volatile("ldmatrix.sync.aligned.m8n8.x4.shared.b16 {%0,%1,%2,%3},[%4];" \
                 : "=r"(r0),"=r"(r1),"=r"(r2),"=r"(r3) : "r"(addr))
#define LDSM_X4T(r0,r1,r2,r3,addr) \
    asm volatile("ldmatrix.sync.aligned.m8n8.x4.trans.shared.b16 {%0,%1,%2,%3},[%4];" \
                 : "=r"(r0),"=r"(r1),"=r"(r2),"=r"(r3) : "r"(addr))
#define LDSM_X2T(r0,r1,addr) \
    asm volatile("ldmatrix.sync.aligned.m8n8.x2.trans.shared.b16 {%0,%1},[%2];" \
                 : "=r"(r0),"=r"(r1) : "r"(addr))
#define MMA16816(d0,d1,d2,d3,a0,a1,a2,a3,b0,b1) \
    asm volatile("mma.sync.aligned.m16n8k16.row.col.f32.bf16.bf16.f32 " \
                 "{%0,%1,%2,%3},{%4,%5,%6,%7},{%8,%9},{%0,%1,%2,%3};" \
                 : "+f"(d0),"+f"(d1),"+f"(d2),"+f"(d3) \
                 : "r"(a0),"r"(a1),"r"(a2),"r"(a3),"r"(b0),"r"(b1))
#define MMA16832F8(d0,d1,d2,d3,a0,a1,a2,a3,b0,b1) \
    asm volatile("mma.sync.aligned.m16n8k32.row.col.f32.e4m3.e4m3.f32 " \
                 "{%0,%1,%2,%3},{%4,%5,%6,%7},{%8,%9},{%0,%1,%2,%3};" \
                 : "+f"(d0),"+f"(d1),"+f"(d2),"+f"(d3) \
                 : "r"(a0),"r"(a1),"r"(a2),"r"(a3),"r"(b0),"r"(b1))

__device__ __forceinline__ uint16_t f2fp8x2(float a, float b) {
    return (uint16_t)__nv_cvt_float2_to_fp8x2(make_float2(a, b), __NV_SATFINITE, __NV_E4M3);
}

// ---------------- conversions ----------------
// x fp32 [b][c][tn] -> fp8-pair units [b][c2][tn]
__global__ void x_to_fp8(const float* __restrict__ x, uint16_t* __restrict__ out)
{
    const ll TN = (ll)Tt * NN;
    int idx = blockIdx.x * blockDim.x + threadIdx.x;
    if (idx >= Bb * C2 * Tt * NN) return;
    int i  = idx & (Tt * NN - 1);
    int r  = idx / (Tt * NN);
    int c2 = r & (C2 - 1);
    int b  = r / C2;
    ll in0 = (ll)b * Cc * TN + (ll)(2 * c2) * TN + i;
    out[idx] = f2fp8x2(x[in0], x[in0 + TN]);
}

// weights W[o][k] fp32 -> fp8-pair units Wt2[k2][o], scaled x32
__global__ void conv_weights_fp8(const float* __restrict__ w1, const float* __restrict__ w2,
                                 const float* __restrict__ w3, const float* __restrict__ w4,
                                 uint16_t* __restrict__ o1, uint16_t* __restrict__ o2,
                                 uint16_t* __restrict__ o3, uint16_t* __restrict__ o4)
{
    const int M1 = C2 * C3, M2 = C2 * Cc;
    int idx = blockIdx.x * blockDim.x + threadIdx.x;
    const float* in; uint16_t* out; int O; int rem;
    if (idx < M1)                { in = w1; out = o1; O = C3; rem = idx; }
    else if (idx < M1 + M2)      { in = w2; out = o2; O = Cc; rem = idx - M1; }
    else if (idx < 2 * M1 + M2)  { in = w3; out = o3; O = C3; rem = idx - M1 - M2; }
    else if (idx < 2 * (M1 + M2)){ in = w4; out = o4; O = Cc; rem = idx - 2 * M1 - M2; }
    else return;
    int o = rem % O, k2 = rem / O;
    float a = in[(ll)o * Cc + 2 * k2]     * 32.f;
    float b = in[(ll)o * Cc + 2 * k2 + 1] * 32.f;
    out[rem] = f2fp8x2(a, b);
}

// ---------------- fp8 tensor-core GEMM: 128x128 tiles, k2-chunks of 32 (=64 k) ----------------
// C[g][o][n] = invScale * sum_k W8[k2][o] X8[g][k2][n]  (+bias, +res)
// Output: exactly one of Cf (fp32, optional res), Cb (bf16), C8 (fp8-pairs, xoscale).
__global__ __launch_bounds__(256, 2) void gemm_fp8(
    const uint16_t* __restrict__ Wt2,   // [K2][ldA]
    const uint16_t* __restrict__ X8,
    float* __restrict__ Cf,
    bf16* __restrict__ Cb,
    uint16_t* __restrict__ C8,
    const float* __restrict__ bias,
    const float* __restrict__ res,
    float invScale, float oscale,
    int K2, int ldA, int gDiv,
    ll xOuter, ll xInner, ll xRow,
    ll cOuter, ll cInner, ll cRow)
{
    __shared__ uint16_t As[3][32][128];
    __shared__ uint16_t Bs[3][32][128];

    int g = blockIdx.z;
    ll gq = g / gDiv, gr = g % gDiv;
    const uint16_t* Xb = X8 + gq * xOuter + gr * xInner;
    ll cbase = gq * cOuter + gr * cInner;

    int n0 = blockIdx.x * 128;
    int o0 = blockIdx.y * 128;

    int tid = threadIdx.x;
    int lane = tid & 31, warp = tid >> 5;
    int wm = warp >> 2, wn = warp & 3;

    uint32_t asb = smem_u32(&As[0][0][0]);
    uint32_t bsb = smem_u32(&Bs[0][0][0]);

    float acc[4][4][4];
    #pragma unroll
    for (int a = 0; a < 4; a++)
        #pragma unroll
        for (int b = 0; b < 4; b++)
            #pragma unroll
            for (int c = 0; c < 4; c++) acc[a][b][c] = 0.f;

    int nkt = K2 / 32;   // 8 for K2=256

    #define ISSUE_TILE(kt, buf) do {                                                     \
        int k0_ = (kt) * 32;                                                             \
        _Pragma("unroll")                                                                \
        for (int i_ = 0; i_ < 2; i_++) {                                                 \
            int idx_ = tid + 256 * i_;                                                   \
            int row_ = idx_ >> 4, ch_ = idx_ & 15;                                       \
            const uint16_t* sA = Wt2 + (ll)(k0_ + row_) * ldA + o0 + ch_ * 8;            \
            uint32_t dA = asb + (buf) * 8192 + row_ * 256 + (((ch_) ^ (row_ & 7)) << 4); \
            CP_ASYNC(dA, sA);                                                            \
            const uint16_t* sB = Xb + (ll)(k0_ + row_) * xRow + n0 + ch_ * 8;            \
            uint32_t dB = bsb + (buf) * 8192 + row_ * 256 + (((ch_) ^ (row_ & 7)) << 4); \
            CP_ASYNC(dB, sB);                                                            \
        }                                                                                \
    } while (0)

    ISSUE_TILE(0, 0);
    CP_COMMIT();
    ISSUE_TILE(1, 1);
    CP_COMMIT();

    int r7 = lane & 7, sub = lane >> 3;
    int brow_lo = lane & 15;

    for (int kt = 0; kt < nkt; kt++) {
        CP_WAIT1();
        __syncthreads();
        if (kt + 2 < nkt) {
            ISSUE_TILE(kt + 2, (kt + 2) % 3);
        }
        CP_COMMIT();
        int buf = kt % 3;
        uint32_t abase = asb + buf * 8192;
        uint32_t bbase = bsb + buf * 8192;

        #pragma unroll
        for (int ks = 0; ks < 2; ks++) {
            uint32_t af[4][4];
            uint32_t bf_[4][2];
            #pragma unroll
            for (int mt = 0; mt < 4; mt++) {
                int krow = ks * 16 + r7 + ((sub >> 1) << 3);
                int mcol = wm * 64 + mt * 16 + ((sub & 1) << 3);
                uint32_t addr = abase + krow * 256 + ((((mcol >> 3)) ^ (krow & 7)) << 4);
                LDSM_X4T(af[mt][0], af[mt][1], af[mt][2], af[mt][3], addr);
            }
            #pragma unroll
            for (int nt = 0; nt < 4; nt++) {
                int brow = ks * 16 + brow_lo;
                int ncol = wn * 32 + nt * 8;
                uint32_t addr = bbase + brow * 256 + ((((ncol >> 3)) ^ (brow & 7)) << 4);
                LDSM_X2T(bf_[nt][0], bf_[nt][1], addr);
            }
            #pragma unroll
            for (int mt = 0; mt < 4; mt++)
                #pragma unroll
                for (int nt = 0; nt < 4; nt++)
                    MMA16832F8(acc[mt][nt][0], acc[mt][nt][1], acc[mt][nt][2], acc[mt][nt][3],
                               af[mt][0], af[mt][1], af[mt][2], af[mt][3],
                               bf_[nt][0], bf_[nt][1]);
        }
    }

    int g4 = lane >> 2, t4 = lane & 3;
    bool even = ((g4 & 1) == 0);
    #pragma unroll
    for (int mt = 0; mt < 4; mt++) {
        #pragma unroll
        for (int nt = 0; nt < 4; nt++) {
            int orow = o0 + wm * 64 + mt * 16 + g4;
            int col  = n0 + wn * 32 + nt * 8 + t4 * 2;
            float b0 = bias ? bias[orow] : 0.f;
            float b1 = bias ? bias[orow + 8] : 0.f;
            float* a = acc[mt][nt];
            float v0 = a[0] * invScale + b0;
            float v1 = a[1] * invScale + b0;
            float v2 = a[2] * invScale + b1;
            float v3 = a[3] * invScale + b1;
            if (C8) {
                v0 *= oscale; v1 *= oscale; v2 *= oscale; v3 *= oscale;
                float p0 = __shfl_xor_sync(0xffffffffu, v0, 4);
                float p1 = __shfl_xor_sync(0xffffffffu, v1, 4);
                float p2 = __shfl_xor_sync(0xffffffffu, v2, 4);
                float p3 = __shfl_xor_sync(0xffffffffu, v3, 4);
                if (even) {
                    uint32_t u0 = (uint32_t)f2fp8x2(v0, p0) | ((uint32_t)f2fp8x2(v1, p1) << 16);
                    uint32_t u1 = (uint32_t)f2fp8x2(v2, p2) | ((uint32_t)f2fp8x2(v3, p3) << 16);
                    ll r2 = cbase + (ll)(orow >> 1) * cRow + col;
                    *(uint32_t*)(C8 + r2) = u0;
                    *(uint32_t*)(C8 + r2 + 4 * cRow) = u1;
                }
            } else if (Cb) {
                ll off0 = cbase + (ll)orow * cRow + col;
                __nv_bfloat162 w0 = __floats2bfloat162_rn(v0, v1);
                __nv_bfloat162 w1 = __floats2bfloat162_rn(v2, v3);
                *reinterpret_cast<__nv_bfloat162*>(Cb + off0) = w0;
                *reinterpret_cast<__nv_bfloat162*>(Cb + off0 + 8 * cRow) = w1;
            } else {
                ll off0 = cbase + (ll)orow * cRow + col;
                ll off1 = off0 + 8 * cRow;
                float2 r0 = make_float2(0.f, 0.f), r1 = make_float2(0.f, 0.f);
                if (res) { r0 = *(const float2*)(res + off0); r1 = *(const float2*)(res + off1); }
                *(float2*)(Cf + off0) = make_float2(v0 + r0.x, v1 + r0.y);
                *(float2*)(Cf + off1) = make_float2(v2 + r1.x, v3 + r1.y);
            }
        }
    }
    #undef ISSUE_TILE
}

// ---------------- spatial softmaxes (bf16 in/out, fp32 math) ----------------
__global__ __launch_bounds__(128) void softmax_q(bf16* __restrict__ p)
{
    int n = blockIdx.x * 128 + threadIdx.x;
    ll base = (ll)blockIdx.z * C3 * NN + (ll)blockIdx.y * Dd * NN + n;
    float v[Dd];
    #pragma unroll
    for (int d = 0; d < Dd; d++) v[d] = __bfloat162float(p[base + (ll)d * NN]);
    float m = v[0];
    #pragma unroll
    for (int d = 1; d < Dd; d++) m = fmaxf(m, v[d]);
    float s = 0.f;
    #pragma unroll
    for (int d = 0; d < Dd; d++) { v[d] = __expf(v[d] - m); s += v[d]; }
    float inv = 0.125f / s;
    #pragma unroll
    for (int d = 0; d < Dd; d++)
        p[base + (ll)d * NN] = __float2bfloat16(v[d] * inv);
}

__global__ __launch_bounds__(256) void softmax_k(bf16* __restrict__ p)
{
    bf16* row = p + (ll)blockIdx.y * C3 * NN + (ll)(Cc + blockIdx.x) * NN;
    int tid = threadIdx.x;
    float v[4];
    float m = -INFINITY;
    #pragma unroll
    for (int k = 0; k < 4; k++) { v[k] = __bfloat162float(row[tid + 256 * k]); m = fmaxf(m, v[k]); }
    __shared__ float red[8];
    #pragma unroll
    for (int o = 16; o; o >>= 1) m = fmaxf(m, __shfl_xor_sync(0xffffffffu, m, o));
    if ((tid & 31) == 0) red[tid >> 5] = m;
    __syncthreads();
    m = red[0];
    #pragma unroll
    for (int wv = 1; wv < 8; wv++) m = fmaxf(m, red[wv]);
    __syncthreads();
    float s = 0.f;
    #pragma unroll
    for (int k = 0; k < 4; k++) { v[k] = __expf(v[k] - m); s += v[k]; }
    #pragma unroll
    for (int o = 16; o; o >>= 1) s += __shfl_xor_sync(0xffffffffu, s, o);
    if ((tid & 31) == 0) red[tid >> 5] = s;
    __syncthreads();
    s = 0.f;
    #pragma unroll
    for (int wv = 0; wv < 8; wv++) s += red[wv];
    float inv = 1.f / s;
    #pragma unroll
    for (int k = 0; k < 4; k++) row[tid + 256 * k] = __float2bfloat16(v[k] * inv);
}

// ---------------- ctx (bf16 mma): ctx_ed[e][d] = sum_n k[d][n] v[e][n] ----------------
__global__ __launch_bounds__(128) void ctx_mma(const bf16* __restrict__ qkv,
                                               bf16* __restrict__ ctx_ed)
{
    int h = blockIdx.x, bt = blockIdx.y;
    const bf16* kbase = qkv + (ll)bt * C3 * NN + (ll)(Cc + h * Dd) * NN;
    const bf16* vbase = qkv + (ll)bt * C3 * NN + (ll)(2 * Cc + h * Dd) * NN;

    __shared__ bf16 Ks[2][64 * 64];
    __shared__ bf16 Vs[2][64 * 64];
    uint32_t ksb = smem_u32(&Ks[0][0]);
    uint32_t vsb = smem_u32(&Vs[0][0]);

    int tid = threadIdx.x;
    int lane = tid & 31, warp = tid >> 5;
    int m0 = warp * 16;

    float acc[8][4] = {};

    #define CTX_ISSUE(c, buf) do {                                                  \
        _Pragma("unroll")                                                           \
        for (int i_ = 0; i_ < 8; i_++) {                                            \
            int idx_ = i_ * 128 + tid;                                              \
            int mat_ = idx_ >> 9;                                                   \
            int rem_ = idx_ & 511;                                                  \
            int row_ = rem_ >> 3, ch_ = rem_ & 7;                                   \
            const bf16* src_ = (mat_ ? vbase : kbase) + (ll)row_ * NN + (c) * 64 + ch_ * 8; \
            uint32_t dst_ = (mat_ ? vsb : ksb) + (buf) * 8192 + row_ * 128 + ((ch_ ^ (row_ & 7)) << 4); \
            CP_ASYNC(dst_, src_);                                                   \
        }                                                                           \
    } while (0)

    CTX_ISSUE(0, 0);
    CP_COMMIT();

    for (int c = 0; c < 16; c++) {
        CP_WAIT0();
        __syncthreads();
        if (c + 1 < 16) { CTX_ISSUE(c + 1, (c + 1) & 1); CP_COMMIT(); }
        int buf = c & 1;
        uint32_t ka = ksb + buf * 8192;
        uint32_t va = vsb + buf * 8192;
        #pragma unroll
        for (int ks = 0; ks < 4; ks++) {
            int k0 = ks * 16;
            uint32_t a0, a1, a2, a3;
            {
                int row = m0 + (lane & 15);
                int ch  = (k0 >> 3) + (lane >> 4);
                uint32_t addr = ka + row * 128 + ((ch ^ (row & 7)) << 4);
                LDSM_X4(a0, a1, a2, a3, addr);
            }
            #pragma unroll
            for (int nb = 0; nb < 4; nb++) {
                int row = nb * 16 + ((lane >> 4) << 3) + (lane & 7);
                int ch  = (k0 >> 3) + ((lane >> 3) & 1);
                uint32_t addr = va + row * 128 + ((ch ^ (row & 7)) << 4);
                uint32_t r0, r1, r2, r3;
                LDSM_X4(r0, r1, r2, r3, addr);
                MMA16816(acc[nb*2][0],   acc[nb*2][1],   acc[nb*2][2],   acc[nb*2][3],
                         a0, a1, a2, a3, r0, r1);
                MMA16816(acc[nb*2+1][0], acc[nb*2+1][1], acc[nb*2+1][2], acc[nb*2+1][3],
                         a0, a1, a2, a3, r2, r3);
            }
        }
    }
    #undef CTX_ISSUE

    bf16* cb = ctx_ed + ((ll)bt * HEADS + h) * (Dd * Dd);
    int g4 = lane >> 2, t4 = lane & 3;
    #pragma unroll
    for (int nt = 0; nt < 8; nt++) {
        int e0 = nt * 8 + t4 * 2;
        int d0 = m0 + g4;
        cb[(e0)     * Dd + d0]     = __float2bfloat16(acc[nt][0]);
        cb[(e0 + 1) * Dd + d0]     = __float2bfloat16(acc[nt][1]);
        cb[(e0)     * Dd + d0 + 8] = __float2bfloat16(acc[nt][2]);
        cb[(e0 + 1) * Dd + d0 + 8] = __float2bfloat16(acc[nt][3]);
    }
}

// ---------------- attn apply (bf16 mma) -> sattn fp8-pairs (x16) ----------------
__global__ __launch_bounds__(256) void attn_apply_mma(const bf16* __restrict__ ctx_ed,
                                                      const bf16* __restrict__ qkv,
                                                      uint16_t* __restrict__ out8)
{
    int n0 = blockIdx.x * 256, h = blockIdx.y, bt = blockIdx.z;
    const bf16* cbase = ctx_ed + ((ll)bt * HEADS + h) * (Dd * Dd);
    const bf16* qbase = qkv + (ll)bt * C3 * NN + (ll)(h * Dd) * NN;

    __shared__ bf16 Asm[64 * 64];
    __shared__ bf16 Bsm[64 * 256];
    uint32_t asb = smem_u32(&Asm[0]);
    uint32_t bsb = smem_u32(&Bsm[0]);

    int tid = threadIdx.x;
    int lane = tid & 31, warp = tid >> 5;
    int wm = warp >> 2, wn = warp & 3;

    #pragma unroll
    for (int i = 0; i < 2; i++) {
        int idx = i * 256 + tid;
        int row = idx >> 3, ch = idx & 7;
        const bf16* src = cbase + row * Dd + ch * 8;
        uint32_t dst = asb + row * 128 + ((ch ^ (row & 7)) << 4);
        CP_ASYNC(dst, src);
    }
    #pragma unroll
    for (int i = 0; i < 8; i++) {
        int idx = i * 256 + tid;
        int row = idx >> 5, ch = idx & 31;
        const bf16* src = qbase + (ll)row * NN + n0 + ch * 8;
        uint32_t dst = bsb + row * 512 + ((ch ^ (row & 7)) << 4);
        CP_ASYNC(dst, src);
    }
    CP_COMMIT();
    CP_WAIT0();
    __syncthreads();

    float acc[2][8][4] = {};
    #pragma unroll
    for (int ks = 0; ks < 4; ks++) {
        int k0 = ks * 16;
        uint32_t af[2][4];
        #pragma unroll
        for (int mt = 0; mt < 2; mt++) {
            int row = wm * 32 + mt * 16 + (lane & 15);
            int ch  = (k0 >> 3) + (lane >> 4);
            uint32_t addr = asb + row * 128 + ((ch ^ (row & 7)) << 4);
            LDSM_X4(af[mt][0], af[mt][1], af[mt][2], af[mt][3], addr);
        }
        #pragma unroll
        for (int nt = 0; nt < 8; nt++) {
            int krow = k0 + (lane & 15);
            int ncol = wn * 64 + nt * 8;
            uint32_t addr = bsb + krow * 512 + (((ncol >> 3) ^ (krow & 7)) << 4);
            uint32_t b0, b1;
            LDSM_X2T(b0, b1, addr);
            #pragma unroll
            for (int mt = 0; mt < 2; mt++)
                MMA16816(acc[mt][nt][0], acc[mt][nt][1], acc[mt][nt][2], acc[mt][nt][3],
                         af[mt][0], af[mt][1], af[mt][2], af[mt][3], b0, b1);
        }
    }

    uint16_t* ob8 = out8 + (ll)bt * C2 * NN + (ll)(h * 32) * NN;
    int g4 = lane >> 2, t4 = lane & 3;
    bool even = ((g4 & 1) == 0);
    #pragma unroll
    for (int mt = 0; mt < 2; mt++) {
        #pragma unroll
        for (int nt = 0; nt < 8; nt++) {
            int erow = wm * 32 + mt * 16 + g4;
            int col  = n0 + wn * 64 + nt * 8 + t4 * 2;
            float v0 = acc[mt][nt][0] * 16.f;
            float v1 = acc[mt][nt][1] * 16.f;
            float v2 = acc[mt][nt][2] * 16.f;
            float v3 = acc[mt][nt][3] * 16.f;
            float p0 = __shfl_xor_sync(0xffffffffu, v0, 4);
            float p1 = __shfl_xor_sync(0xffffffffu, v1, 4);
            float p2 = __shfl_xor_sync(0xffffffffu, v2, 4);
            float p3 = __shfl_xor_sync(0xffffffffu, v3, 4);
            if (even) {
                uint32_t u0 = (uint32_t)f2fp8x2(v0, p0) | ((uint32_t)f2fp8x2(v1, p1) << 16);
                uint32_t u1 = (uint32_t)f2fp8x2(v2, p2) | ((uint32_t)f2fp8x2(v3, p3) << 16);
                *(uint32_t*)(ob8 + (ll)(erow >> 1) * NN + col) = u0;
                *(uint32_t*)(ob8 + (ll)((erow >> 1) + 4) * NN + col) = u1;
            }
        }
    }
}

// ---------------- fused temporal attention -> tout fp8-pairs (x128) ----------------
#define ST 8
#define TSMEM (2 * 16 * 64 * 9 * 4 + 256 * 9 * 4)   // ks + vs + attw = 82944 B

__global__ __launch_bounds__(128) void temporal_fused(const bf16* __restrict__ tqkv,
                                                      uint16_t* __restrict__ out8)
{
    extern __shared__ float tsm[];
    float* ks   = tsm;
    float* vs   = tsm + 16 * 64 * 9;
    float* attw = vs  + 16 * 64 * 9;

    int b = blockIdx.z, hh = blockIdx.y;
    int s0 = blockIdx.x * ST;
    const bf16* kb = tqkv + ((ll)b * C3 + Cc + hh * Dd) * (Tt * NN);
    const bf16* vb = tqkv + ((ll)b * C3 + 2 * Cc + hh * Dd) * (Tt * NN);
    int tid = threadIdx.x;

    #pragma unroll
    for (int l = 0; l < (16 * 64 * ST) / 128; l++) {
        int idx = l * 128 + tid;
        int s = idx & (ST - 1);
        int rest = idx >> 3;
        int d = rest & 63, j = rest >> 6;
        ll goff = (ll)d * (Tt * NN) + j * NN + s0 + s;
        ks[rest * 9 + s] = __bfloat162float(kb[goff]);
        vs[rest * 9 + s] = __bfloat162float(vb[goff]);
    }
    __syncthreads();

    int sl = tid & (ST - 1);
    int i  = tid >> 3;

    {
        const bf16* qb = tqkv + ((ll)b * C3 + hh * Dd) * (Tt * NN)
                       + (ll)i * NN + s0 + sl;
        float acc[16];
        #pragma unroll
        for (int j = 0; j < 16; j++) acc[j] = 0.f;
        for (int d = 0; d < 64; d++) {
            float qv = __bfloat162float(qb[(ll)d * (Tt * NN)]) * 0.125f;
            #pragma unroll
            for (int j = 0; j < 16; j++)
                acc[j] += qv * ks[(j * 64 + d) * 9 + sl];
        }
        float m = acc[0];
        #pragma unroll
        for (int j = 1; j < 16; j++) m = fmaxf(m, acc[j]);
        float sum = 0.f;
        #pragma unroll
        for (int j = 0; j < 16; j++) { acc[j] = __expf(acc[j] - m); sum += acc[j]; }
        float inv = 1.f / sum;
        #pragma unroll
        for (int j = 0; j < 16; j++)
            attw[(i * 16 + j) * 9 + sl] = acc[j] * inv;
    }
    __syncthreads();

    int dg = i;
    const ll TN = (ll)Tt * NN;
    // channels dg*4..dg*4+3 -> pair rows c2 = hh*32+dg*2 and +1
    uint16_t* ob8 = out8 + ((ll)b * C2 + hh * 32 + dg * 2) * TN + s0 + sl;
    for (int ii = 0; ii < 16; ii++) {
        float a0 = 0.f, a1 = 0.f, a2 = 0.f, a3 = 0.f;
        #pragma unroll
        for (int j = 0; j < 16; j++) {
            float av = attw[(ii * 16 + j) * 9 + sl];
            a0 += av * vs[(j * 64 + dg * 4 + 0) * 9 + sl];
            a1 += av * vs[(j * 64 + dg * 4 + 1) * 9 + sl];
            a2 += av * vs[(j * 64 + dg * 4 + 2) * 9 + sl];
            a3 += av * vs[(j * 64 + dg * 4 + 3) * 9 + sl];
        }
        ll t_off = (ll)ii * NN;
        ob8[t_off]      = f2fp8x2(a0 * 128.f, a1 * 128.f);
        ob8[t_off + TN] = f2fp8x2(a2 * 128.f, a3 * 128.f);
    }
}

// ---------------- launch ----------------
extern "C" void kernel_launch(void* const* d_in, const int* in_sizes, int n_in,
                              void* d_out, int out_size)
{
    const float* x      = (const float*)d_in[0];
    const float* w_sqkv = (const float*)d_in[1];
    const float* w_sout = (const float*)d_in[2];
    const float* b_sout = (const float*)d_in[3];
    const float* w_tqkv = (const float*)d_in[4];
    const float* w_tout = (const float*)d_in[5];
    float* out = (float*)d_out;

    uint16_t *w8_sqkv, *w8_sout, *w8_tqkv, *w8_tout, *x8, *sattn8, *h18, *tout8;
    bf16 *sqkv, *ctx_ed, *tqkv;
    cudaGetSymbolAddress((void**)&w8_sqkv, g_w8_sqkv);
    cudaGetSymbolAddress((void**)&w8_sout, g_w8_sout);
    cudaGetSymbolAddress((void**)&w8_tqkv, g_w8_tqkv);
    cudaGetSymbolAddress((void**)&w8_tout, g_w8_tout);
    cudaGetSymbolAddress((void**)&x8,      g_x8);
    cudaGetSymbolAddress((void**)&sqkv,    g_sqkv);
    cudaGetSymbolAddress((void**)&ctx_ed,  g_ctx_ed);
    cudaGetSymbolAddress((void**)&sattn8,  g_sattn8);
    cudaGetSymbolAddress((void**)&h18,     g_h18);
    cudaGetSymbolAddress((void**)&tqkv,    g_tqkv);
    cudaGetSymbolAddress((void**)&tout8,   g_tout8);

    static int attr_set = 0;
    if (!attr_set) {
        cudaFuncSetAttribute(temporal_fused, cudaFuncAttributeMaxDynamicSharedMemorySize, TSMEM);
        attr_set = 1;
    }

    const ll TN = (ll)Tt * NN;

    // conversions
    int xN = Bb * C2 * Tt * NN;
    x_to_fp8<<<(xN + 255) / 256, 256>>>(x, x8);
    conv_weights_fp8<<<(2 * (C2 * C3 + C2 * Cc) + 255) / 256, 256>>>(
        w_sqkv, w_sout, w_tqkv, w_tout, w8_sqkv, w8_sout, w8_tqkv, w8_tout);

    // 1) spatial qkv -> sqkv bf16 [bt][o][n]   (w x32, x x1 -> inv 1/32)
    gemm_fp8<<<dim3(NN / 128, C3 / 128, BT), 256>>>(
        w8_sqkv, x8, nullptr, sqkv, nullptr, nullptr, nullptr,
        1.f / 32.f, 1.f,
        C2, C3, Tt,
        (ll)C2 * TN, NN, TN,
        (ll)Tt * C3 * NN, (ll)C3 * NN, NN);

    // 2-3) softmaxes
    softmax_q<<<dim3(NN / 128, HEADS, BT), 128>>>(sqkv);
    softmax_k<<<dim3(Cc, BT), 256>>>(sqkv);

    // 4) ctx
    ctx_mma<<<dim3(HEADS, BT), 128>>>(sqkv, ctx_ed);

    // 5) apply -> sattn fp8-pairs (x16)
    attn_apply_mma<<<dim3(NN / 256, HEADS, BT), 256>>>(ctx_ed, sqkv, sattn8);

    // 6) spatial proj + bias -> h1 fp8-pairs (inv 1/(32*16), out x64)
    gemm_fp8<<<dim3(NN / 128, Cc / 128, BT), 256>>>(
        w8_sout, sattn8, nullptr, nullptr, h18, b_sout, nullptr,
        1.f / 512.f, 64.f,
        C2, Cc, Tt,
        (ll)Tt * C2 * NN, (ll)C2 * NN, NN,
        (ll)C2 * TN, NN, TN);

    // 7) temporal qkv -> tqkv bf16 (inv 1/(32*64))
    gemm_fp8<<<dim3((int)(TN / 128), C3 / 128, Bb), 256>>>(
        w8_tqkv, h18, nullptr, tqkv, nullptr, nullptr, nullptr,
        1.f / 2048.f, 1.f,
        C2, C3, 1,
        (ll)C2 * TN, 0, TN,
        (ll)C3 * TN, 0, TN);

    // 8) fused temporal attention -> tout fp8-pairs (x128)
    temporal_fused<<<dim3(NN / ST, HEADS, Bb), 128, TSMEM>>>(tqkv, tout8);

    // 9) temporal proj + residual -> out fp32 (inv 1/(32*128))
    gemm_fp8<<<dim3((int)(TN / 128), Cc / 128, Bb), 256>>>(
        w8_tout, tout8, out, nullptr, nullptr, nullptr, x,
        1.f / 4096.f, 1.f,
        C2, Cc, 1,
        (ll)C2 * TN, 0, TN,
        (ll)Cc * TN, 0, TN);
}